// round 5
// baseline (speedup 1.0000x reference)
#include <cuda_runtime.h>
#include <math.h>

#define BB   32
#define TT   2048
#define HIDD 1024
#define OUTD 1024
#define DVV  1024
#define HALF 512

// ---- scratch (no allocation allowed; __device__ globals) ----
__device__ float g_query[BB * OUTD];   // [B, OUT]
__device__ float g_weff[OUTD];         // W1 @ W2  -> [OUT]
__device__ float g_c0;                 // b1 . W2 + b2
__device__ float g_scores[BB * TT];    // masked scores

__device__ __forceinline__ float tanh_approx(float x) {
    float y;
    asm("tanh.approx.f32 %0, %1;" : "=f"(y) : "f"(x));
    return y;
}

// ---------------------------------------------------------------------------
// Kernel 1: query[b,:] = hidden[b,:] @ Wq + bq        grid = B, block = 256
// Wq is [HID, OUT] row-major (already transposed, per reference).
// ---------------------------------------------------------------------------
__global__ void k_query(const float* __restrict__ hidden,
                        const float* __restrict__ Wq,
                        const float* __restrict__ bq) {
    __shared__ float hs[HIDD];
    const int b = blockIdx.x;
    for (int k = threadIdx.x; k < HIDD; k += 256)
        hs[k] = hidden[b * HIDD + k];
    __syncthreads();

    const int o = threadIdx.x;
    float a0 = 0.f, a1 = 0.f, a2 = 0.f, a3 = 0.f;
    for (int k = 0; k < HIDD; k++) {
        const float h = hs[k];
        const float* w = Wq + (size_t)k * OUTD;
        a0 = fmaf(h, w[o],       a0);
        a1 = fmaf(h, w[o + 256], a1);
        a2 = fmaf(h, w[o + 512], a2);
        a3 = fmaf(h, w[o + 768], a3);
    }
    float* q = g_query + (size_t)b * OUTD;
    q[o]       = a0 + bq[o];
    q[o + 256] = a1 + bq[o + 256];
    q[o + 512] = a2 + bq[o + 512];
    q[o + 768] = a3 + bq[o + 768];
}

// ---------------------------------------------------------------------------
// Kernel 2: w_eff = W1 @ W2 (OUT-vector), c0 = b1.W2 + b2
// grid = 128 blocks * 8 warps = 1024 warps, one warp per k.
// ---------------------------------------------------------------------------
__global__ void k_weff(const float* __restrict__ W1,
                       const float* __restrict__ b1,
                       const float* __restrict__ W2,
                       const float* __restrict__ b2) {
    __shared__ float w2s[HALF];
    for (int j = threadIdx.x; j < HALF; j += 256) w2s[j] = W2[j];
    __syncthreads();

    const int warp = threadIdx.x >> 5;
    const int lane = threadIdx.x & 31;
    const int k = blockIdx.x * 8 + warp;

    float acc = 0.f;
    const float* row = W1 + (size_t)k * HALF;
    #pragma unroll 4
    for (int j = lane; j < HALF; j += 32)
        acc = fmaf(row[j], w2s[j], acc);
    #pragma unroll
    for (int off = 16; off; off >>= 1)
        acc += __shfl_xor_sync(0xFFFFFFFFu, acc, off);
    if (lane == 0) g_weff[k] = acc;

    if (blockIdx.x == 0 && warp == 0) {
        float c = 0.f;
        for (int j = lane; j < HALF; j += 32)
            c = fmaf(b1[j], w2s[j], c);
        #pragma unroll
        for (int off = 16; off; off >>= 1)
            c += __shfl_xor_sync(0xFFFFFFFFu, c, off);
        if (lane == 0) g_c0 = c + b2[0];
    }
}

// ---------------------------------------------------------------------------
// Kernel 3: scores[b,t] = sum_k tanh(key[b,t,k] + query[b,k]) * w_eff[k] + c0
//           masked to -inf for t >= seq_len[b] (skips the 256MB read there).
// grid = (T/8, B), block = 256 (8 warps, 1 warp per t-row).
// ---------------------------------------------------------------------------
__global__ void k_scores(const float* __restrict__ key,
                         const int* __restrict__ seq_lens) {
    __shared__ float qs[OUTD];
    __shared__ float ws[OUTD];
    const int b = blockIdx.y;
    for (int k = threadIdx.x; k < OUTD; k += 256) {
        qs[k] = g_query[(size_t)b * OUTD + k];
        ws[k] = g_weff[k];
    }
    __syncthreads();

    const int warp = threadIdx.x >> 5;
    const int lane = threadIdx.x & 31;
    const int t = blockIdx.x * 8 + warp;
    const int sl = seq_lens[b];

    if (t >= sl) {
        if (lane == 0) g_scores[(size_t)b * TT + t] = -INFINITY;
        return;
    }

    const float4* row = reinterpret_cast<const float4*>(
        key + ((size_t)b * TT + t) * OUTD);
    const float4* q4 = reinterpret_cast<const float4*>(qs);
    const float4* w4 = reinterpret_cast<const float4*>(ws);

    float acc0 = 0.f, acc1 = 0.f;
    #pragma unroll
    for (int i = 0; i < 8; i++) {
        const int idx = i * 32 + lane;
        const float4 kv = row[idx];
        const float4 q  = q4[idx];
        const float4 w  = w4[idx];
        acc0 = fmaf(tanh_approx(kv.x + q.x), w.x, acc0);
        acc1 = fmaf(tanh_approx(kv.y + q.y), w.y, acc1);
        acc0 = fmaf(tanh_approx(kv.z + q.z), w.z, acc0);
        acc1 = fmaf(tanh_approx(kv.w + q.w), w.w, acc1);
    }
    float acc = acc0 + acc1;
    #pragma unroll
    for (int off = 16; off; off >>= 1)
        acc += __shfl_xor_sync(0xFFFFFFFFu, acc, off);
    if (lane == 0) g_scores[(size_t)b * TT + t] = acc + g_c0;
}

// ---------------------------------------------------------------------------
// Kernel 4: softmax over T per batch (masked entries -> exactly 0).
// grid = B, block = 256 (8 elements / thread).
// ---------------------------------------------------------------------------
__global__ void k_softmax(float* __restrict__ attn_out) {
    __shared__ float red[256];
    const int b = blockIdx.x;
    const int tid = threadIdx.x;

    float local[8];
    float m = -INFINITY;
    #pragma unroll
    for (int i = 0; i < 8; i++) {
        local[i] = g_scores[(size_t)b * TT + tid + i * 256];
        m = fmaxf(m, local[i]);
    }
    red[tid] = m;
    __syncthreads();
    for (int s = 128; s; s >>= 1) {
        if (tid < s) red[tid] = fmaxf(red[tid], red[tid + s]);
        __syncthreads();
    }
    m = red[0];
    __syncthreads();

    float sum = 0.f;
    #pragma unroll
    for (int i = 0; i < 8; i++) {
        local[i] = expf(local[i] - m);   // exp(-inf - m) == 0 for masked
        sum += local[i];
    }
    red[tid] = sum;
    __syncthreads();
    for (int s = 128; s; s >>= 1) {
        if (tid < s) red[tid] += red[tid + s];
        __syncthreads();
    }
    const float inv = 1.0f / red[0];
    #pragma unroll
    for (int i = 0; i < 8; i++)
        attn_out[(size_t)b * TT + tid + i * 256] = local[i] * inv;
}

// ---------------------------------------------------------------------------
// Kernel 5: context[b,d] = sum_{t < seq_len} attn[b,t] * value[b,t,d]
// grid = (DV/64, B), block = 256: 4 t-groups x 64 d-lanes.
// ---------------------------------------------------------------------------
__global__ void k_context(const float* __restrict__ value,
                          const int* __restrict__ seq_lens,
                          const float* __restrict__ attn,
                          float* __restrict__ context) {
    __shared__ float as[TT];
    __shared__ float red[4][64];
    const int b  = blockIdx.y;
    const int d0 = blockIdx.x * 64;
    const int sl = seq_lens[b];

    for (int t = threadIdx.x; t < sl; t += 256)
        as[t] = attn[(size_t)b * TT + t];
    __syncthreads();

    const int tg = threadIdx.x >> 6;   // 0..3
    const int dd = threadIdx.x & 63;   // 0..63

    const float* vbase = value + (size_t)b * TT * DVV + d0 + dd;
    float acc = 0.f;
    #pragma unroll 4
    for (int t = tg; t < sl; t += 4)
        acc = fmaf(as[t], vbase[(size_t)t * DVV], acc);

    red[tg][dd] = acc;
    __syncthreads();
    if (tg == 0) {
        context[(size_t)b * DVV + d0 + dd] =
            red[0][dd] + red[1][dd] + red[2][dd] + red[3][dd];
    }
}

// ---------------------------------------------------------------------------
extern "C" void kernel_launch(void* const* d_in, const int* in_sizes, int n_in,
                              void* d_out, int out_size) {
    const float* hidden   = (const float*)d_in[0];
    const float* key      = (const float*)d_in[1];
    const float* value    = (const float*)d_in[2];
    const int*   seq_lens = (const int*)  d_in[3];
    const float* Wq       = (const float*)d_in[4];
    const float* bq       = (const float*)d_in[5];
    const float* W1       = (const float*)d_in[6];
    const float* b1       = (const float*)d_in[7];
    const float* W2       = (const float*)d_in[8];
    const float* b2       = (const float*)d_in[9];

    float* out     = (float*)d_out;
    float* context = out;                 // [B, DV]
    float* attn    = out + BB * DVV;      // [B, T]

    k_query  <<<BB, 256>>>(hidden, Wq, bq);
    k_weff   <<<OUTD / 8, 256>>>(W1, b1, W2, b2);
    k_scores <<<dim3(TT / 8, BB), 256>>>(key, seq_lens);
    k_softmax<<<BB, 256>>>(attn);
    k_context<<<dim3(DVV / 64, BB), 256>>>(value, seq_lens, attn, context);
}

// round 7
// speedup vs baseline: 2.6314x; 2.6314x over previous
#include <cuda_runtime.h>
#include <math.h>

#define BB     32
#define TT     2048
#define HIDD   1024
#define OUTD   1024
#define DVV    1024
#define HALF   512
#define KSPLIT 32
#define KCH    32      // HIDD / KSPLIT

// ---- scratch (__device__ globals; no allocation allowed) ----
__device__ float g_qpart[KSPLIT][BB][OUTD];  // query partials per k-split
__device__ float g_query[BB * OUTD];         // [B, OUT]
__device__ float g_weff[OUTD];               // W1 @ W2
__device__ float g_c0;                       // b1 . W2 + b2
__device__ float g_scores[BB * TT];          // raw scores (only t < sl written)

__device__ __forceinline__ float tanh_approx(float x) {
    float y;
    asm("tanh.approx.f32 %0, %1;" : "=f"(y) : "f"(x));
    return y;
}

// ---------------------------------------------------------------------------
// Kernel 1: query partials. grid = (OUT/256, KSPLIT) = (4, 32), block = 256.
// Each block: k-chunk of 32, o-chunk of 256, ALL 32 batches in registers.
// Wq (4 MB) is read from DRAM exactly once across the whole grid. FMA-bound.
// ---------------------------------------------------------------------------
__global__ void k_qpart(const float* __restrict__ hidden,
                        const float* __restrict__ Wq) {
    __shared__ float hs[KCH][BB];   // hs[k][b], b contiguous for LDS.128
    const int ks = blockIdx.y;
    const int k0 = ks * KCH;
    const int tid = threadIdx.x;

    for (int idx = tid; idx < KCH * BB; idx += 256) {
        const int k = idx >> 5;
        const int b = idx & 31;
        hs[k][b] = hidden[b * HIDD + k0 + k];
    }
    __syncthreads();

    const int o = blockIdx.x * 256 + tid;
    float acc[BB];
    #pragma unroll
    for (int b = 0; b < BB; b++) acc[b] = 0.f;

    #pragma unroll 4
    for (int k = 0; k < KCH; k++) {
        const float w = Wq[(size_t)(k0 + k) * OUTD + o];
        const float4* h4 = reinterpret_cast<const float4*>(hs[k]);
        #pragma unroll
        for (int b4 = 0; b4 < BB / 4; b4++) {
            const float4 h = h4[b4];
            acc[b4 * 4 + 0] = fmaf(h.x, w, acc[b4 * 4 + 0]);
            acc[b4 * 4 + 1] = fmaf(h.y, w, acc[b4 * 4 + 1]);
            acc[b4 * 4 + 2] = fmaf(h.z, w, acc[b4 * 4 + 2]);
            acc[b4 * 4 + 3] = fmaf(h.w, w, acc[b4 * 4 + 3]);
        }
    }
    #pragma unroll
    for (int b = 0; b < BB; b++)
        g_qpart[ks][b][o] = acc[b];
}

// ---------------------------------------------------------------------------
// Kernel 2 (fused): blocks [0,128) compute w_eff = W1@W2 and c0;
//                   blocks [128,160) reduce query partials + bq.
// ---------------------------------------------------------------------------
__global__ void k_qred_weff(const float* __restrict__ bq,
                            const float* __restrict__ W1,
                            const float* __restrict__ b1,
                            const float* __restrict__ W2,
                            const float* __restrict__ b2) {
    if (blockIdx.x < 128) {
        __shared__ float w2s[HALF];
        for (int j = threadIdx.x; j < HALF; j += 256) w2s[j] = W2[j];
        __syncthreads();

        const int warp = threadIdx.x >> 5;
        const int lane = threadIdx.x & 31;
        const int k = blockIdx.x * 8 + warp;

        float acc = 0.f;
        const float* row = W1 + (size_t)k * HALF;
        #pragma unroll 4
        for (int j = lane; j < HALF; j += 32)
            acc = fmaf(row[j], w2s[j], acc);
        #pragma unroll
        for (int off = 16; off; off >>= 1)
            acc += __shfl_xor_sync(0xFFFFFFFFu, acc, off);
        if (lane == 0) g_weff[k] = acc;

        if (blockIdx.x == 0 && warp == 0) {
            float c = 0.f;
            for (int j = lane; j < HALF; j += 32)
                c = fmaf(b1[j], w2s[j], c);
            #pragma unroll
            for (int off = 16; off; off >>= 1)
                c += __shfl_xor_sync(0xFFFFFFFFu, c, off);
            if (lane == 0) g_c0 = c + b2[0];
        }
    } else {
        const int b = blockIdx.x - 128;
        const int tid = threadIdx.x;
        #pragma unroll
        for (int j = 0; j < 4; j++) {
            const int oo = tid + j * 256;
            float acc = bq[oo];
            #pragma unroll
            for (int s = 0; s < KSPLIT; s++)
                acc += g_qpart[s][b][oo];
            g_query[b * OUTD + oo] = acc;
        }
    }
}

// ---------------------------------------------------------------------------
// Kernel 3: scores[b,t] = sum_k tanh(key[b,t,k]+q[b,k]) * w_eff[k] + c0
// grid = (T/32, B), block = 256 (8 warps x 4 rows each). Early-exit on mask.
// ---------------------------------------------------------------------------
__global__ void k_scores(const float* __restrict__ key,
                         const int* __restrict__ seq_lens) {
    const int b = blockIdx.y;
    const int sl = seq_lens[b];
    if (blockIdx.x * 32 >= sl) return;   // whole block masked: skip smem load too

    __shared__ float4 qs[OUTD / 4];
    __shared__ float4 ws[OUTD / 4];
    for (int k = threadIdx.x; k < OUTD / 4; k += 256) {
        qs[k] = reinterpret_cast<const float4*>(g_query + (size_t)b * OUTD)[k];
        ws[k] = reinterpret_cast<const float4*>(g_weff)[k];
    }
    __syncthreads();

    const int warp = threadIdx.x >> 5;
    const int lane = threadIdx.x & 31;
    const float c0 = g_c0;
    const int tbase = blockIdx.x * 32 + warp * 4;

    #pragma unroll
    for (int r = 0; r < 4; r++) {
        const int t = tbase + r;
        if (t >= sl) break;

        const float4* row = reinterpret_cast<const float4*>(
            key + ((size_t)b * TT + t) * OUTD);

        float acc0 = 0.f, acc1 = 0.f;
        #pragma unroll
        for (int i = 0; i < 8; i++) {
            const int idx = i * 32 + lane;
            const float4 kv = __ldcs(row + idx);     // read-once: stream past L2
            const float4 q  = qs[idx];
            const float4 w  = ws[idx];
            acc0 = fmaf(tanh_approx(kv.x + q.x), w.x, acc0);
            acc1 = fmaf(tanh_approx(kv.y + q.y), w.y, acc1);
            acc0 = fmaf(tanh_approx(kv.z + q.z), w.z, acc0);
            acc1 = fmaf(tanh_approx(kv.w + q.w), w.w, acc1);
        }
        float acc = acc0 + acc1;
        #pragma unroll
        for (int off = 16; off; off >>= 1)
            acc += __shfl_xor_sync(0xFFFFFFFFu, acc, off);
        if (lane == 0) g_scores[(size_t)b * TT + t] = acc + c0;
    }
}

// ---------------------------------------------------------------------------
// Kernel 4 (fused softmax + context):
//   each block recomputes softmax of scores[b,:sl] in smem (cheap, L2-fed),
//   keeps unnormalized exp in smem, scales by 1/sum at the end.
//   grid = (DV/128, B) = (8, 32), block = 256 (8 warps, 32 lanes x float4).
//   blockIdx.x == 0 also writes the attn output row (0 for masked t).
// ---------------------------------------------------------------------------
__global__ void k_ctx(const float* __restrict__ value,
                      const int* __restrict__ seq_lens,
                      float* __restrict__ attn,
                      float* __restrict__ context) {
    __shared__ float  as[TT];
    __shared__ float  red[256];
    __shared__ float4 red4[8][32];

    const int b  = blockIdx.y;
    const int sl = seq_lens[b];
    const int tid = threadIdx.x;

    // load raw scores + max
    float m = -INFINITY;
    for (int t = tid; t < sl; t += 256) {
        const float s = g_scores[(size_t)b * TT + t];
        as[t] = s;
        m = fmaxf(m, s);
    }
    red[tid] = m;
    __syncthreads();
    for (int s = 128; s; s >>= 1) {
        if (tid < s) red[tid] = fmaxf(red[tid], red[tid + s]);
        __syncthreads();
    }
    m = red[0];
    __syncthreads();

    // exp + sum (unnormalized exp stays in smem)
    float sum = 0.f;
    for (int t = tid; t < sl; t += 256) {
        const float e = __expf(as[t] - m);
        as[t] = e;
        sum += e;
    }
    red[tid] = sum;
    __syncthreads();
    for (int s = 128; s; s >>= 1) {
        if (tid < s) red[tid] += red[tid + s];
        __syncthreads();
    }
    const float inv = 1.0f / red[0];

    // attn output (only one block per batch)
    if (blockIdx.x == 0) {
        for (int t = tid; t < TT; t += 256)
            attn[(size_t)b * TT + t] = (t < sl) ? as[t] * inv : 0.f;
    }

    // context: warp w handles rows t = w, w+8, ...; lane covers 4 d's (float4)
    const int warp = tid >> 5;
    const int lane = tid & 31;
    const int d0 = blockIdx.x * 128;

    const float4* vbase = reinterpret_cast<const float4*>(
        value + (size_t)b * TT * DVV + d0) + lane;

    float4 acc = {0.f, 0.f, 0.f, 0.f};
    #pragma unroll 4
    for (int t = warp; t < sl; t += 8) {
        const float  a = as[t];
        const float4 v = __ldcs(vbase + (size_t)t * (DVV / 4));
        acc.x = fmaf(a, v.x, acc.x);
        acc.y = fmaf(a, v.y, acc.y);
        acc.z = fmaf(a, v.z, acc.z);
        acc.w = fmaf(a, v.w, acc.w);
    }
    red4[warp][lane] = acc;
    __syncthreads();

    if (warp == 0) {
        float4 s = red4[0][lane];
        #pragma unroll
        for (int w = 1; w < 8; w++) {
            const float4 r = red4[w][lane];
            s.x += r.x; s.y += r.y; s.z += r.z; s.w += r.w;
        }
        const float4 sv = {s.x * inv, s.y * inv, s.z * inv, s.w * inv};
        reinterpret_cast<float4*>(context + (size_t)b * DVV + d0)[lane] = sv;
    }
}

// ---------------------------------------------------------------------------
extern "C" void kernel_launch(void* const* d_in, const int* in_sizes, int n_in,
                              void* d_out, int out_size) {
    const float* hidden   = (const float*)d_in[0];
    const float* key      = (const float*)d_in[1];
    const float* value    = (const float*)d_in[2];
    const int*   seq_lens = (const int*)  d_in[3];
    const float* Wq       = (const float*)d_in[4];
    const float* bq       = (const float*)d_in[5];
    const float* W1       = (const float*)d_in[6];
    const float* b1       = (const float*)d_in[7];
    const float* W2       = (const float*)d_in[8];
    const float* b2       = (const float*)d_in[9];

    float* out     = (float*)d_out;
    float* context = out;                 // [B, DV]
    float* attn    = out + BB * DVV;      // [B, T]

    k_qpart    <<<dim3(OUTD / 256, KSPLIT), 256>>>(hidden, Wq);
    k_qred_weff<<<160, 256>>>(bq, W1, b1, W2, b2);
    k_scores   <<<dim3(TT / 32, BB), 256>>>(key, seq_lens);
    k_ctx      <<<dim3(DVV / 128, BB), 256>>>(value, seq_lens, attn, context);
}

// round 8
// speedup vs baseline: 4.1150x; 1.5638x over previous
#include <cuda_runtime.h>
#include <math.h>

#define BB     32
#define TT     2048
#define HIDD   1024
#define OUTD   1024
#define DVV    1024
#define HALF   512
#define KSPLIT 32
#define KCH    32      // HIDD / KSPLIT
#define TCH    64      // t-chunk for context partials
#define NCH    (TT / TCH)   // 32 chunks

// ---- scratch (__device__ globals; no allocation allowed) ----
__device__ float g_qpart[KSPLIT][BB][OUTD];   // query partials per k-split
__device__ float g_query[BB * OUTD];          // [B, OUT]
__device__ float g_weff[OUTD];                // W1 @ W2
__device__ float g_c0;                        // b1 . W2 + b2
__device__ float g_scores[BB * TT];           // raw scores (only t < sl written)
__device__ float g_cpart[NCH][BB][DVV];       // context partials per t-chunk

__device__ __forceinline__ float tanh_approx(float x) {
    float y;
    asm("tanh.approx.f32 %0, %1;" : "=f"(y) : "f"(x));
    return y;
}

// ---------------------------------------------------------------------------
// Kernel 1: query partials. grid = (OUT/256, KSPLIT) = (4, 32), block = 256.
// Wq (4 MB) read from DRAM exactly once across the grid. FMA-bound.
// ---------------------------------------------------------------------------
__global__ void k_qpart(const float* __restrict__ hidden,
                        const float* __restrict__ Wq) {
    __shared__ float hs[KCH][BB];
    const int ks = blockIdx.y;
    const int k0 = ks * KCH;
    const int tid = threadIdx.x;

    for (int idx = tid; idx < KCH * BB; idx += 256) {
        const int k = idx >> 5;
        const int b = idx & 31;
        hs[k][b] = hidden[b * HIDD + k0 + k];
    }
    __syncthreads();

    const int o = blockIdx.x * 256 + tid;
    float acc[BB];
    #pragma unroll
    for (int b = 0; b < BB; b++) acc[b] = 0.f;

    #pragma unroll 4
    for (int k = 0; k < KCH; k++) {
        const float w = Wq[(size_t)(k0 + k) * OUTD + o];
        const float4* h4 = reinterpret_cast<const float4*>(hs[k]);
        #pragma unroll
        for (int b4 = 0; b4 < BB / 4; b4++) {
            const float4 h = h4[b4];
            acc[b4 * 4 + 0] = fmaf(h.x, w, acc[b4 * 4 + 0]);
            acc[b4 * 4 + 1] = fmaf(h.y, w, acc[b4 * 4 + 1]);
            acc[b4 * 4 + 2] = fmaf(h.z, w, acc[b4 * 4 + 2]);
            acc[b4 * 4 + 3] = fmaf(h.w, w, acc[b4 * 4 + 3]);
        }
    }
    #pragma unroll
    for (int b = 0; b < BB; b++)
        g_qpart[ks][b][o] = acc[b];
}

// ---------------------------------------------------------------------------
// Kernel 2 (fused): blocks [0,128) -> w_eff = W1@W2 and c0;
//                   blocks [128,160) -> reduce query partials + bq.
// ---------------------------------------------------------------------------
__global__ void k_qred_weff(const float* __restrict__ bq,
                            const float* __restrict__ W1,
                            const float* __restrict__ b1,
                            const float* __restrict__ W2,
                            const float* __restrict__ b2) {
    if (blockIdx.x < 128) {
        __shared__ float w2s[HALF];
        for (int j = threadIdx.x; j < HALF; j += 256) w2s[j] = W2[j];
        __syncthreads();

        const int warp = threadIdx.x >> 5;
        const int lane = threadIdx.x & 31;
        const int k = blockIdx.x * 8 + warp;

        float acc = 0.f;
        const float* row = W1 + (size_t)k * HALF;
        #pragma unroll 4
        for (int j = lane; j < HALF; j += 32)
            acc = fmaf(row[j], w2s[j], acc);
        #pragma unroll
        for (int off = 16; off; off >>= 1)
            acc += __shfl_xor_sync(0xFFFFFFFFu, acc, off);
        if (lane == 0) g_weff[k] = acc;

        if (blockIdx.x == 0 && warp == 0) {
            float c = 0.f;
            for (int j = lane; j < HALF; j += 32)
                c = fmaf(b1[j], w2s[j], c);
            #pragma unroll
            for (int off = 16; off; off >>= 1)
                c += __shfl_xor_sync(0xFFFFFFFFu, c, off);
            if (lane == 0) g_c0 = c + b2[0];
        }
    } else {
        const int b = blockIdx.x - 128;
        const int tid = threadIdx.x;
        #pragma unroll
        for (int j = 0; j < 4; j++) {
            const int oo = tid + j * 256;
            float acc = bq[oo];
            #pragma unroll
            for (int s = 0; s < KSPLIT; s++)
                acc += g_qpart[s][b][oo];
            g_query[b * OUTD + oo] = acc;
        }
    }
}

// ---------------------------------------------------------------------------
// Kernel 3: scores[b,t] = sum_k tanh(key[b,t,k]+q[b,k]) * w_eff[k] + c0
// grid = (T/32, B), block = 256 (8 warps x 4 rows). Mask early-exit.
// ---------------------------------------------------------------------------
__global__ void k_scores(const float* __restrict__ key,
                         const int* __restrict__ seq_lens) {
    const int b = blockIdx.y;
    const int sl = seq_lens[b];
    if (blockIdx.x * 32 >= sl) return;

    __shared__ float4 qs[OUTD / 4];
    __shared__ float4 ws[OUTD / 4];
    for (int k = threadIdx.x; k < OUTD / 4; k += 256) {
        qs[k] = reinterpret_cast<const float4*>(g_query + (size_t)b * OUTD)[k];
        ws[k] = reinterpret_cast<const float4*>(g_weff)[k];
    }
    __syncthreads();

    const int warp = threadIdx.x >> 5;
    const int lane = threadIdx.x & 31;
    const float c0 = g_c0;
    const int tbase = blockIdx.x * 32 + warp * 4;

    #pragma unroll
    for (int r = 0; r < 4; r++) {
        const int t = tbase + r;
        if (t >= sl) break;

        const float4* row = reinterpret_cast<const float4*>(
            key + ((size_t)b * TT + t) * OUTD);

        float acc0 = 0.f, acc1 = 0.f;
        #pragma unroll
        for (int i = 0; i < 8; i++) {
            const int idx = i * 32 + lane;
            const float4 kv = __ldcs(row + idx);   // read-once stream
            const float4 q  = qs[idx];
            const float4 w  = ws[idx];
            acc0 = fmaf(tanh_approx(kv.x + q.x), w.x, acc0);
            acc1 = fmaf(tanh_approx(kv.y + q.y), w.y, acc1);
            acc0 = fmaf(tanh_approx(kv.z + q.z), w.z, acc0);
            acc1 = fmaf(tanh_approx(kv.w + q.w), w.w, acc1);
        }
        float acc = acc0 + acc1;
        #pragma unroll
        for (int off = 16; off; off >>= 1)
            acc += __shfl_xor_sync(0xFFFFFFFFu, acc, off);
        if (lane == 0) g_scores[(size_t)b * TT + t] = acc + c0;
    }
}

// ---------------------------------------------------------------------------
// Kernel 4: softmax per batch -> normalized attn into d_out (zeros for t>=sl).
// grid = B, block = 256.
// ---------------------------------------------------------------------------
__global__ void k_softmax(const int* __restrict__ seq_lens,
                          float* __restrict__ attn) {
    __shared__ float as[TT];
    __shared__ float red[256];
    const int b  = blockIdx.x;
    const int sl = seq_lens[b];
    const int tid = threadIdx.x;

    float m = -INFINITY;
    for (int t = tid; t < sl; t += 256) {
        const float s = g_scores[(size_t)b * TT + t];
        as[t] = s;
        m = fmaxf(m, s);
    }
    red[tid] = m;
    __syncthreads();
    for (int s = 128; s; s >>= 1) {
        if (tid < s) red[tid] = fmaxf(red[tid], red[tid + s]);
        __syncthreads();
    }
    m = red[0];
    __syncthreads();

    float sum = 0.f;
    for (int t = tid; t < sl; t += 256) {
        const float e = __expf(as[t] - m);
        as[t] = e;
        sum += e;
    }
    red[tid] = sum;
    __syncthreads();
    for (int s = 128; s; s >>= 1) {
        if (tid < s) red[tid] += red[tid + s];
        __syncthreads();
    }
    const float inv = 1.0f / red[0];

    for (int t = tid; t < TT; t += 256)
        attn[(size_t)b * TT + t] = (t < sl) ? as[t] * inv : 0.f;
}

// ---------------------------------------------------------------------------
// Kernel 5: context partials. grid = (T/64, B) = (32, 32) = 1024 blocks.
// Each block: 64 t-rows x full 1024 d (thread -> float4). Masked chunks exit.
// ---------------------------------------------------------------------------
__global__ void k_ctxpart(const float* __restrict__ value,
                          const int* __restrict__ seq_lens,
                          const float* __restrict__ attn) {
    const int b  = blockIdx.y;
    const int sl = seq_lens[b];
    const int c  = blockIdx.x;
    const int t0 = c * TCH;
    if (t0 >= sl) return;

    __shared__ float as[TCH];
    const int tid = threadIdx.x;
    if (tid < TCH)
        as[tid] = attn[(size_t)b * TT + t0 + tid];   // 0 beyond sl
    __syncthreads();

    const int nt = min(TCH, sl - t0);
    const float4* vbase = reinterpret_cast<const float4*>(
        value + ((size_t)b * TT + t0) * DVV) + tid;

    float4 acc = {0.f, 0.f, 0.f, 0.f};
    #pragma unroll 8
    for (int t = 0; t < nt; t++) {
        const float  a = as[t];
        const float4 v = __ldcs(vbase + (size_t)t * (DVV / 4));
        acc.x = fmaf(a, v.x, acc.x);
        acc.y = fmaf(a, v.y, acc.y);
        acc.z = fmaf(a, v.z, acc.z);
        acc.w = fmaf(a, v.w, acc.w);
    }
    reinterpret_cast<float4*>(&g_cpart[c][b][0])[tid] = acc;
}

// ---------------------------------------------------------------------------
// Kernel 6: reduce context partials (fixed order -> deterministic).
// grid = B, block = 256, thread -> float4 of d.
// ---------------------------------------------------------------------------
__global__ void k_ctxred(const int* __restrict__ seq_lens,
                         float* __restrict__ context) {
    const int b  = blockIdx.x;
    const int sl = seq_lens[b];
    const int nch = (sl + TCH - 1) / TCH;
    const int tid = threadIdx.x;

    float4 acc = {0.f, 0.f, 0.f, 0.f};
    for (int c = 0; c < nch; c++) {
        const float4 p = reinterpret_cast<const float4*>(&g_cpart[c][b][0])[tid];
        acc.x += p.x; acc.y += p.y; acc.z += p.z; acc.w += p.w;
    }
    reinterpret_cast<float4*>(context + (size_t)b * DVV)[tid] = acc;
}

// ---------------------------------------------------------------------------
extern "C" void kernel_launch(void* const* d_in, const int* in_sizes, int n_in,
                              void* d_out, int out_size) {
    const float* hidden   = (const float*)d_in[0];
    const float* key      = (const float*)d_in[1];
    const float* value    = (const float*)d_in[2];
    const int*   seq_lens = (const int*)  d_in[3];
    const float* Wq       = (const float*)d_in[4];
    const float* bq       = (const float*)d_in[5];
    const float* W1       = (const float*)d_in[6];
    const float* b1       = (const float*)d_in[7];
    const float* W2       = (const float*)d_in[8];
    const float* b2       = (const float*)d_in[9];

    float* out     = (float*)d_out;
    float* context = out;                 // [B, DV]
    float* attn    = out + BB * DVV;      // [B, T]

    k_qpart    <<<dim3(OUTD / 256, KSPLIT), 256>>>(hidden, Wq);
    k_qred_weff<<<160, 256>>>(bq, W1, b1, W2, b2);
    k_scores   <<<dim3(TT / 32, BB), 256>>>(key, seq_lens);
    k_softmax  <<<BB, 256>>>(seq_lens, attn);
    k_ctxpart  <<<dim3(NCH, BB), 256>>>(value, seq_lens, attn);
    k_ctxred   <<<BB, 256>>>(seq_lens, context);
}